// round 8
// baseline (speedup 1.0000x reference)
#include <cuda_runtime.h>
#include <cstdint>
#include <math.h>

// Problem constants
#define BWIN   2048
#define SEQ    64
#define DIM    256
#define HEADS  8
#define HD     32
#define NW     64
#define KDIM   256
#define TBL    225
#define CPBH   512

// Scratch (device globals)
__device__ float g_Q[BWIN * HEADS * SEQ * HD];
__device__ float g_K[BWIN * HEADS * SEQ * HD];
__device__ float g_V[BWIN * HEADS * SEQ * HD];
__device__ float g_O[BWIN * SEQ * DIM];
__device__ float g_table[TBL * HEADS];
__device__ float g_bias[HEADS * SEQ * SEQ];
__device__ float g_bm[NW * HEADS * SEQ * SEQ];   // fused bias+mask, 8MB

// SW128 swizzle on byte offsets (128B rows)
#define SWZ(b) ((b) ^ (((b) >> 3) & 0x70))

__device__ __forceinline__ uint32_t smem_u32(const void* p) {
    uint32_t a;
    asm("{ .reg .u64 t; cvta.to.shared.u64 t, %1; cvt.u32.u64 %0, t; }"
        : "=r"(a) : "l"(p));
    return a;
}

#define CP16(dst_u32, src_ptr) \
    asm volatile("cp.async.cg.shared.global [%0], [%1], 16;" \
        :: "r"(dst_u32), "l"(src_ptr) : "memory")
#define CP_COMMIT() asm volatile("cp.async.commit_group;" ::: "memory")
#define CP_WAIT0()  asm volatile("cp.async.wait_group 0;" ::: "memory")
#define CP_WAIT1()  asm volatile("cp.async.wait_group 1;" ::: "memory")

__device__ __forceinline__ uint32_t tf32_rna(float x) {
    uint32_t r;
    asm("cvt.rna.tf32.f32 %0, %1;" : "=r"(r) : "f"(x));
    return r;
}

__device__ __forceinline__ void hilo(float f, uint32_t& h, uint32_t& l) {
    h = tf32_rna(f);
    l = tf32_rna(f - __uint_as_float(h));
}

__device__ __forceinline__ void mma1688(float* c,
    uint32_t a0, uint32_t a1, uint32_t a2, uint32_t a3,
    uint32_t b0, uint32_t b1)
{
    asm volatile(
        "mma.sync.aligned.m16n8k8.row.col.f32.tf32.tf32.f32 "
        "{%0,%1,%2,%3},{%4,%5,%6,%7},{%8,%9},{%0,%1,%2,%3};"
        : "+f"(c[0]), "+f"(c[1]), "+f"(c[2]), "+f"(c[3])
        : "r"(a0), "r"(a1), "r"(a2), "r"(a3), "r"(b0), "r"(b1));
}

// ---------------------------------------------------------------------------
// Kernel 1: CPB MLP
// ---------------------------------------------------------------------------
__global__ __launch_bounds__(128) void cpb_table_kernel(
    const float* __restrict__ w1, const float* __restrict__ b1,
    const float* __restrict__ w2, const float* __restrict__ coords)
{
    int p = blockIdx.x;
    float c0 = coords[2 * p + 0];
    float c1 = coords[2 * p + 1];
    float acc[HEADS];
#pragma unroll
    for (int h = 0; h < HEADS; ++h) acc[h] = 0.f;

    for (int j = threadIdx.x; j < CPBH; j += 128) {
        float hid = fmaf(w1[2 * j], c0, fmaf(w1[2 * j + 1], c1, b1[j]));
        hid = fmaxf(hid, 0.f);
#pragma unroll
        for (int h = 0; h < HEADS; ++h)
            acc[h] = fmaf(hid, w2[h * CPBH + j], acc[h]);
    }
    int lane = threadIdx.x & 31, warp = threadIdx.x >> 5;
#pragma unroll
    for (int h = 0; h < HEADS; ++h)
#pragma unroll
        for (int off = 16; off; off >>= 1)
            acc[h] += __shfl_xor_sync(0xffffffffu, acc[h], off);

    __shared__ float red[4][HEADS];
    if (lane == 0)
#pragma unroll
        for (int h = 0; h < HEADS; ++h) red[warp][h] = acc[h];
    __syncthreads();
    if (threadIdx.x < HEADS) {
        float s = red[0][threadIdx.x] + red[1][threadIdx.x] +
                  red[2][threadIdx.x] + red[3][threadIdx.x];
        g_table[p * HEADS + threadIdx.x] = s;
    }
}

// ---------------------------------------------------------------------------
// Kernel 2: bias gather + 16*sigmoid
// ---------------------------------------------------------------------------
__global__ __launch_bounds__(256) void bias_gather_kernel(const int* __restrict__ rel_idx)
{
    int i = blockIdx.x * 256 + threadIdx.x;
    if (i >= HEADS * SEQ * SEQ) return;
    int h = i >> 12;
    int ij = i & 4095;
    float t = g_table[rel_idx[ij] * HEADS + h];
    g_bias[i] = 16.f / (1.f + expf(-t));
}

// ---------------------------------------------------------------------------
// Kernel 2b: fuse bias[h] + mask[w] -> g_bm[w][h][ij]
// ---------------------------------------------------------------------------
__global__ __launch_bounds__(256) void bm_fuse_kernel(const float* __restrict__ mask)
{
    int i = blockIdx.x * 256 + threadIdx.x;
    if (i >= NW * HEADS * SEQ * SEQ) return;
    int wh = i >> 12;
    int ij = i & 4095;
    int w = wh >> 3, h = wh & 7;
    g_bm[i] = g_bias[h * 4096 + ij] + mask[w * 4096 + ij];
}

// ---------------------------------------------------------------------------
// 3xTF32 mma.sync GEMM, cp.async double-buffered fp32 stages.
// CTA 128x128, 128 threads (4 warps of 64x64), BK=32, K=256 (8 stages).
// ---------------------------------------------------------------------------
#define GSMEM_TOTAL 65536

__global__ __launch_bounds__(128, 2) void mma_gemm(
    const float* __restrict__ A_in, const float* __restrict__ B,
    const float* __restrict__ q_bias, const float* __restrict__ v_bias,
    const float* __restrict__ pb, float* __restrict__ out, int mode)
{
    extern __shared__ char sm[];
    uint32_t sb = smem_u32(sm);
    const float* A = (mode == 0) ? A_in : g_O;
    int tid = threadIdx.x;
    int lane = tid & 31, warp = tid >> 5;
    int m0 = blockIdx.y * 128;
    int n0 = blockIdx.x * 128;
    int wm = (warp >> 1) * 64;
    int wn = (warp & 1) * 64;

    float acc[4][8][4];
#pragma unroll
    for (int mi = 0; mi < 4; ++mi)
#pragma unroll
        for (int ni = 0; ni < 8; ++ni)
#pragma unroll
            for (int q = 0; q < 4; ++q) acc[mi][ni][q] = 0.f;

    int lrow = tid >> 3;     // 0..15
    int lc4 = tid & 7;       // 0..7
    int g = lane >> 2;       // 0..7
    int tk = lane & 3;       // 0..3

#define ISSUE_STAGE(ko) do { \
    uint32_t ab = sb + (uint32_t)(((ko) & 1) * 32768); \
    uint32_t bb = ab + 16384u; \
    _Pragma("unroll") \
    for (int q = 0; q < 8; ++q) { \
        int r = lrow + 16 * q; \
        uint32_t so = SWZ((uint32_t)(r * 128 + lc4 * 16)); \
        CP16(ab + so, A + (size_t)(m0 + r) * KDIM + (ko) * 32 + lc4 * 4); \
        CP16(bb + so, B + (size_t)(n0 + r) * KDIM + (ko) * 32 + lc4 * 4); \
    } \
    CP_COMMIT(); \
} while (0)

    ISSUE_STAGE(0);

    for (int ko = 0; ko < 8; ++ko) {
        if (ko < 7) { ISSUE_STAGE(ko + 1); CP_WAIT1(); }
        else        { CP_WAIT0(); }
        __syncthreads();

        const char* sA = sm + (ko & 1) * 32768;
        const char* sB = sA + 16384;
#pragma unroll
        for (int kk = 0; kk < 32; kk += 8) {
            uint32_t Ah[4][4], Al[4][4];
#pragma unroll
            for (int mi = 0; mi < 4; ++mi) {
                int r0 = wm + mi * 16 + g;
                int r1 = r0 + 8;
                float a0 = *(const float*)(sA + SWZ((uint32_t)(r0 * 128 + (kk + tk) * 4)));
                float a1 = *(const float*)(sA + SWZ((uint32_t)(r1 * 128 + (kk + tk) * 4)));
                float a2 = *(const float*)(sA + SWZ((uint32_t)(r0 * 128 + (kk + tk + 4) * 4)));
                float a3 = *(const float*)(sA + SWZ((uint32_t)(r1 * 128 + (kk + tk + 4) * 4)));
                hilo(a0, Ah[mi][0], Al[mi][0]);
                hilo(a1, Ah[mi][1], Al[mi][1]);
                hilo(a2, Ah[mi][2], Al[mi][2]);
                hilo(a3, Ah[mi][3], Al[mi][3]);
            }
#pragma unroll
            for (int ni = 0; ni < 8; ++ni) {
                int nr = wn + ni * 8 + g;
                float b0 = *(const float*)(sB + SWZ((uint32_t)(nr * 128 + (kk + tk) * 4)));
                float b1 = *(const float*)(sB + SWZ((uint32_t)(nr * 128 + (kk + tk + 4) * 4)));
                uint32_t bh0, bl0, bh1, bl1;
                hilo(b0, bh0, bl0);
                hilo(b1, bh1, bl1);
#pragma unroll
                for (int mi = 0; mi < 4; ++mi) {
                    mma1688(acc[mi][ni], Ah[mi][0], Ah[mi][1], Ah[mi][2], Ah[mi][3], bh0, bh1);
                    mma1688(acc[mi][ni], Al[mi][0], Al[mi][1], Al[mi][2], Al[mi][3], bh0, bh1);
                    mma1688(acc[mi][ni], Ah[mi][0], Ah[mi][1], Ah[mi][2], Ah[mi][3], bl0, bl1);
                }
            }
        }
        __syncthreads();
    }

    // Epilogue
#pragma unroll
    for (int mi = 0; mi < 4; ++mi) {
#pragma unroll
        for (int ni = 0; ni < 8; ++ni) {
            int r = m0 + wm + mi * 16 + g;        // rows r and r+8
            int c = n0 + wn + ni * 8 + 2 * tk;    // cols c, c+1
            if (mode == 0) {
                int which = c >> 8;
                int h = (c >> 5) & 7;
                int d = c & 31;
                float b0, b1;
                if (which == 0)      { b0 = q_bias[c];       b1 = q_bias[c + 1]; }
                else if (which == 2) { b0 = v_bias[c - 512]; b1 = v_bias[c - 511]; }
                else                 { b0 = 0.f; b1 = 0.f; }
                float* baseP = (which == 0) ? g_Q : (which == 1) ? g_K : g_V;
                int bw0 = r >> 6, n_0 = r & 63;
                int bw1 = (r + 8) >> 6, n_1 = (r + 8) & 63;
                float2 v0 = make_float2(acc[mi][ni][0] + b0, acc[mi][ni][1] + b1);
                float2 v1 = make_float2(acc[mi][ni][2] + b0, acc[mi][ni][3] + b1);
                *(float2*)(baseP + (size_t)((bw0 * 8 + h) * 64 + n_0) * 32 + d) = v0;
                *(float2*)(baseP + (size_t)((bw1 * 8 + h) * 64 + n_1) * 32 + d) = v1;
            } else {
                float b0 = pb[c], b1 = pb[c + 1];
                float2 v0 = make_float2(acc[mi][ni][0] + b0, acc[mi][ni][1] + b1);
                float2 v1 = make_float2(acc[mi][ni][2] + b0, acc[mi][ni][3] + b1);
                *(float2*)(out + (size_t)r * 256 + c) = v0;
                *(float2*)(out + (size_t)(r + 8) * 256 + c) = v1;
            }
        }
    }
}

// ---------------------------------------------------------------------------
// Fused attention with mma.sync (3xTF32), WITH cosine L2 normalization.
// Grid: 4096 CTAs: CTA = (window b = blockIdx.x>>1, head group of 4).
// 256 threads = 8 warps; pair p = warp>>1 handles head hgrp+p; the two warps
// of a pair split the 64 rows (32 each).
// Per-pair smem: q(64x36 f32) k v = 27648B. P (64x68) overlays q+k after QK.
// ---------------------------------------------------------------------------
#define ATT_PAIRB 27648
#define ATT_SMEM  (4 * ATT_PAIRB)

__global__ __launch_bounds__(256, 2) void attn_mma(const float* __restrict__ logit_scale)
{
    extern __shared__ char sm[];
    int tid = threadIdx.x;
    int lane = tid & 31, warp = tid >> 5;
    int b = blockIdx.x >> 1;
    int hgrp = (blockIdx.x & 1) * 4;
    int pair = warp >> 1;
    int h = hgrp + pair;
    int wp = warp & 1;           // warp index within pair
    int wrow = wp * 32;
    int g = lane >> 2, tk = lane & 3;

    char* pbse = sm + pair * ATT_PAIRB;
    float* qs = (float*)pbse;            // 64 x stride36
    float* ks = qs + 64 * 36;
    float* vs = ks + 64 * 36;
    float* Ps = (float*)pbse;            // 64 x stride68, overlays q+k

    // load q,k,v (fp32) via cp.async; 64 threads per pair
    {
        int ptid = tid & 63;
        const float* Qg = g_Q + (size_t)(b * 8 + h) * 2048;
        const float* Kg = g_K + (size_t)(b * 8 + h) * 2048;
        const float* Vg = g_V + (size_t)(b * 8 + h) * 2048;
        uint32_t qa = smem_u32(qs), ka = smem_u32(ks), va = smem_u32(vs);
#pragma unroll
        for (int i = 0; i < 8; ++i) {
            int idx = ptid + 64 * i;
            int r = idx >> 3, c4 = idx & 7;
            uint32_t do_ = (uint32_t)(r * 144 + c4 * 16);
            CP16(qa + do_, Qg + r * 32 + c4 * 4);
            CP16(ka + do_, Kg + r * 32 + c4 * 4);
            CP16(va + do_, Vg + r * 32 + c4 * 4);
        }
        CP_COMMIT();
        CP_WAIT0();
    }
    __syncthreads();

    // ---- cosine attention: L2-normalize q and k rows ----
    // each warp of the pair handles 64 of the 128 rows; lane = dim
    for (int r = wp; r < 128; r += 2) {
        float* row = (r < 64) ? (qs + r * 36) : (ks + (r - 64) * 36);
        float vv = row[lane];
        float ss = vv * vv;
#pragma unroll
        for (int off = 16; off; off >>= 1)
            ss += __shfl_xor_sync(0xffffffffu, ss, off);
        float inv = 1.f / fmaxf(sqrtf(ss), 1e-12f);
        row[lane] = vv * inv;
    }
    __syncthreads();

    float sc = __expf(fminf(logit_scale[h], 4.6051701859880913f));

    // ---- QK^T (3xTF32): warp computes rows wrow..wrow+31 x cols 0..63 ----
    float acc[2][8][4];
#pragma unroll
    for (int mi = 0; mi < 2; ++mi)
#pragma unroll
        for (int ni = 0; ni < 8; ++ni)
#pragma unroll
            for (int q = 0; q < 4; ++q) acc[mi][ni][q] = 0.f;

#pragma unroll
    for (int kk = 0; kk < 32; kk += 8) {
        uint32_t Ah[2][4], Al[2][4];
#pragma unroll
        for (int mi = 0; mi < 2; ++mi) {
            int r0 = wrow + mi * 16 + g;
            int r1 = r0 + 8;
            hilo(qs[r0 * 36 + kk + tk],     Ah[mi][0], Al[mi][0]);
            hilo(qs[r1 * 36 + kk + tk],     Ah[mi][1], Al[mi][1]);
            hilo(qs[r0 * 36 + kk + tk + 4], Ah[mi][2], Al[mi][2]);
            hilo(qs[r1 * 36 + kk + tk + 4], Ah[mi][3], Al[mi][3]);
        }
#pragma unroll
        for (int ni = 0; ni < 8; ++ni) {
            int nr = ni * 8 + g;
            uint32_t bh0, bl0, bh1, bl1;
            hilo(ks[nr * 36 + kk + tk],     bh0, bl0);
            hilo(ks[nr * 36 + kk + tk + 4], bh1, bl1);
#pragma unroll
            for (int mi = 0; mi < 2; ++mi) {
                mma1688(acc[mi][ni], Ah[mi][0], Ah[mi][1], Ah[mi][2], Ah[mi][3], bh0, bh1);
                mma1688(acc[mi][ni], Al[mi][0], Al[mi][1], Al[mi][2], Al[mi][3], bh0, bh1);
                mma1688(acc[mi][ni], Ah[mi][0], Ah[mi][1], Ah[mi][2], Ah[mi][3], bl0, bl1);
            }
        }
    }

    // ---- logits + softmax (registers + quad shuffles) ----
    const float* bm = g_bm + (size_t)(((b & (NW - 1)) * 8 + h)) * 4096;
#pragma unroll
    for (int mi = 0; mi < 2; ++mi) {
        int rA = wrow + mi * 16 + g;
        int rB = rA + 8;
        float mxA = -1e30f, mxB = -1e30f;
#pragma unroll
        for (int ni = 0; ni < 8; ++ni) {
            int c = ni * 8 + 2 * tk;
            float2 bA = *(const float2*)(bm + rA * 64 + c);
            float2 bB = *(const float2*)(bm + rB * 64 + c);
            acc[mi][ni][0] = fmaf(sc, acc[mi][ni][0], bA.x);
            acc[mi][ni][1] = fmaf(sc, acc[mi][ni][1], bA.y);
            acc[mi][ni][2] = fmaf(sc, acc[mi][ni][2], bB.x);
            acc[mi][ni][3] = fmaf(sc, acc[mi][ni][3], bB.y);
            mxA = fmaxf(mxA, fmaxf(acc[mi][ni][0], acc[mi][ni][1]));
            mxB = fmaxf(mxB, fmaxf(acc[mi][ni][2], acc[mi][ni][3]));
        }
        mxA = fmaxf(mxA, __shfl_xor_sync(0xffffffffu, mxA, 1));
        mxA = fmaxf(mxA, __shfl_xor_sync(0xffffffffu, mxA, 2));
        mxB = fmaxf(mxB, __shfl_xor_sync(0xffffffffu, mxB, 1));
        mxB = fmaxf(mxB, __shfl_xor_sync(0xffffffffu, mxB, 2));
        float sA = 0.f, sB = 0.f;
#pragma unroll
        for (int ni = 0; ni < 8; ++ni) {
            acc[mi][ni][0] = __expf(acc[mi][ni][0] - mxA);
            acc[mi][ni][1] = __expf(acc[mi][ni][1] - mxA);
            acc[mi][ni][2] = __expf(acc[mi][ni][2] - mxB);
            acc[mi][ni][3] = __expf(acc[mi][ni][3] - mxB);
            sA += acc[mi][ni][0] + acc[mi][ni][1];
            sB += acc[mi][ni][2] + acc[mi][ni][3];
        }
        sA += __shfl_xor_sync(0xffffffffu, sA, 1);
        sA += __shfl_xor_sync(0xffffffffu, sA, 2);
        sB += __shfl_xor_sync(0xffffffffu, sB, 1);
        sB += __shfl_xor_sync(0xffffffffu, sB, 2);
        float iA = 1.f / sA, iB = 1.f / sB;
#pragma unroll
        for (int ni = 0; ni < 8; ++ni) {
            acc[mi][ni][0] *= iA;
            acc[mi][ni][1] *= iA;
            acc[mi][ni][2] *= iB;
            acc[mi][ni][3] *= iB;
        }
    }

    __syncthreads();   // everyone done reading q/k before P overlays them

    // store P (fp32, stride 68)
#pragma unroll
    for (int mi = 0; mi < 2; ++mi) {
        int rA = wrow + mi * 16 + g;
        int rB = rA + 8;
#pragma unroll
        for (int ni = 0; ni < 8; ++ni) {
            int c = ni * 8 + 2 * tk;
            *(float2*)(Ps + rA * 68 + c) = make_float2(acc[mi][ni][0], acc[mi][ni][1]);
            *(float2*)(Ps + rB * 68 + c) = make_float2(acc[mi][ni][2], acc[mi][ni][3]);
        }
    }
    __syncthreads();

    // ---- AV (3xTF32): out rows wrow..+31 x dims 0..31, k over 64 tokens ----
    float o[2][4][4];
#pragma unroll
    for (int mi = 0; mi < 2; ++mi)
#pragma unroll
        for (int ni = 0; ni < 4; ++ni)
#pragma unroll
            for (int q = 0; q < 4; ++q) o[mi][ni][q] = 0.f;

#pragma unroll
    for (int kk = 0; kk < 64; kk += 8) {
        uint32_t Ph[2][4], Pl[2][4];
#pragma unroll
        for (int mi = 0; mi < 2; ++mi) {
            int r0 = wrow + mi * 16 + g;
            int r1 = r0 + 8;
            hilo(Ps[r0 * 68 + kk + tk],     Ph[mi][0], Pl[mi][0]);
            hilo(Ps[r1 * 68 + kk + tk],     Ph[mi][1], Pl[mi][1]);
            hilo(Ps[r0 * 68 + kk + tk + 4], Ph[mi][2], Pl[mi][2]);
            hilo(Ps[r1 * 68 + kk + tk + 4], Ph[mi][3], Pl[mi][3]);
        }
#pragma unroll
        for (int ni = 0; ni < 4; ++ni) {
            int d = ni * 8 + g;
            uint32_t vh0, vl0, vh1, vl1;
            hilo(vs[(kk + tk) * 36 + d],     vh0, vl0);
            hilo(vs[(kk + tk + 4) * 36 + d], vh1, vl1);
#pragma unroll
            for (int mi = 0; mi < 2; ++mi) {
                mma1688(o[mi][ni], Ph[mi][0], Ph[mi][1], Ph[mi][2], Ph[mi][3], vh0, vh1);
                mma1688(o[mi][ni], Pl[mi][0], Pl[mi][1], Pl[mi][2], Pl[mi][3], vh0, vh1);
                mma1688(o[mi][ni], Ph[mi][0], Ph[mi][1], Ph[mi][2], Ph[mi][3], vl0, vl1);
            }
        }
    }

    // write O
    float* Og = g_O + (size_t)b * 64 * 256 + h * 32;
#pragma unroll
    for (int mi = 0; mi < 2; ++mi) {
        int r0 = wrow + mi * 16 + g;
        int r1 = r0 + 8;
#pragma unroll
        for (int ni = 0; ni < 4; ++ni) {
            int c = ni * 8 + 2 * tk;
            *(float2*)(Og + (size_t)r0 * 256 + c) = make_float2(o[mi][ni][0], o[mi][ni][1]);
            *(float2*)(Og + (size_t)r1 * 256 + c) = make_float2(o[mi][ni][2], o[mi][ni][3]);
        }
    }
}

// ---------------------------------------------------------------------------
extern "C" void kernel_launch(void* const* d_in, const int* in_sizes, int n_in,
                              void* d_out, int out_size)
{
    const float* x           = (const float*)d_in[0];
    const float* mask        = (const float*)d_in[1];
    const float* qkv_w       = (const float*)d_in[2];
    const float* q_bias      = (const float*)d_in[3];
    const float* v_bias      = (const float*)d_in[4];
    const float* logit_scale = (const float*)d_in[5];
    const float* cpb_w1      = (const float*)d_in[6];
    const float* cpb_b1      = (const float*)d_in[7];
    const float* cpb_w2      = (const float*)d_in[8];
    const float* proj_w      = (const float*)d_in[9];
    const float* proj_b      = (const float*)d_in[10];
    const float* coords      = (const float*)d_in[11];
    const int*   rel_idx     = (const int*)d_in[12];
    float* out = (float*)d_out;

    static int configured = 0;
    if (!configured) {
        cudaFuncSetAttribute(mma_gemm, cudaFuncAttributeMaxDynamicSharedMemorySize,
                             GSMEM_TOTAL);
        cudaFuncSetAttribute(attn_mma, cudaFuncAttributeMaxDynamicSharedMemorySize,
                             ATT_SMEM);
        configured = 1;
    }

    cpb_table_kernel<<<TBL, 128>>>(cpb_w1, cpb_b1, cpb_w2, coords);
    bias_gather_kernel<<<(HEADS * SEQ * SEQ + 255) / 256, 256>>>(rel_idx);
    bm_fuse_kernel<<<(NW * HEADS * SEQ * SEQ + 255) / 256, 256>>>(mask);
    mma_gemm<<<dim3(6, 1024), 128, GSMEM_TOTAL>>>(x, qkv_w, q_bias, v_bias,
                                                  nullptr, nullptr, 0);
    attn_mma<<<BWIN * 2, 256, ATT_SMEM>>>(logit_scale);
    mma_gemm<<<dim3(2, 1024), 128, GSMEM_TOTAL>>>(nullptr, proj_w, nullptr, nullptr,
                                                  proj_b, out, 1);
}